// round 4
// baseline (speedup 1.0000x reference)
#include <cuda_runtime.h>
#include <math.h>

// Problem dims (fixed by setup_inputs)
#define MAXN 100000
#define MAXB 256
#define D1 3
#define D2 50
#define D3 15
#define D2P 52   // D2 padded to multiple of 4
#define D3P 16   // D3 padded to multiple of 4
#define D5 10
#define NC 6

// ---------------- device scratch (no allocations allowed) ----------------
__device__ float g_x2sum[MAXN * D3];
__device__ float g_cnt[MAXN];
__device__ float g_gsum[MAXB * D3];
__device__ float g_zsum[MAXB * D3];
__device__ float g_gcnt[MAXB];

// ---------------- zero accumulators ----------------
__global__ void zero_kernel() {
    int tid = blockIdx.x * blockDim.x + threadIdx.x;
    int stride = gridDim.x * blockDim.x;
    for (int t = tid; t < MAXN * D3; t += stride) g_x2sum[t] = 0.0f;
    for (int t = tid; t < MAXN; t += stride) g_cnt[t] = 0.0f;
    for (int t = tid; t < MAXB * D3; t += stride) { g_gsum[t] = 0.0f; g_zsum[t] = 0.0f; }
    for (int t = tid; t < MAXB; t += stride) g_gcnt[t] = 0.0f;
}

// ---------------- shared-memory layout for edge kernel weights ----------------
// all offsets are multiples of 4 floats (16B) so float4 LDS works
#define OFF_EW1 0                       // [9][52]  = 468
#define OFF_EB1 (OFF_EW1 + 9 * D2P)     // 468, [52]
#define OFF_EW2 (OFF_EB1 + D2P)         // 520, [50][16] = 800
#define OFF_EB2 (OFF_EW2 + D2 * D3P)    // 1320, [16]
#define OFF_NW1 (OFF_EB2 + D3P)         // 1336, [18][52] = 936
#define OFF_NB1 (OFF_NW1 + 18 * D2P)    // 2272, [52]
#define OFF_NW2 (OFF_NB1 + D2P)         // 2324, [50][16] = 800
#define OFF_NB2 (OFF_NW2 + D2 * D3P)    // 3124, [16]
#define SW_TOTAL (OFF_NB2 + D3P)        // 3140 floats = 12560 B

// ---------------- edge kernel: edge MLP + node MLP + scatter ----------------
__global__ void edge_kernel(
    const float* __restrict__ x,
    const int* __restrict__ row,
    const int* __restrict__ col,
    const float* __restrict__ ea,
    const float* __restrict__ ew1, const float* __restrict__ eb1,
    const float* __restrict__ ew2, const float* __restrict__ eb2,
    const float* __restrict__ nw1, const float* __restrict__ nb1,
    const float* __restrict__ nw2, const float* __restrict__ nb2,
    int E)
{
    __shared__ __align__(16) float sw[SW_TOTAL];

    // zero pads first, then fill with remapped (padded-stride) weights
    for (int t = threadIdx.x; t < SW_TOTAL; t += blockDim.x) sw[t] = 0.0f;
    __syncthreads();
    for (int t = threadIdx.x; t < 9 * D2; t += blockDim.x) {
        int i = t / D2, j = t % D2;
        sw[OFF_EW1 + i * D2P + j] = ew1[t];
    }
    for (int t = threadIdx.x; t < D2; t += blockDim.x) sw[OFF_EB1 + t] = eb1[t];
    for (int t = threadIdx.x; t < D2 * D3; t += blockDim.x) {
        int j = t / D3, k = t % D3;
        sw[OFF_EW2 + j * D3P + k] = ew2[t];
    }
    for (int t = threadIdx.x; t < D3; t += blockDim.x) sw[OFF_EB2 + t] = eb2[t];
    for (int t = threadIdx.x; t < 18 * D2; t += blockDim.x) {
        int i = t / D2, j = t % D2;
        sw[OFF_NW1 + i * D2P + j] = nw1[t];
    }
    for (int t = threadIdx.x; t < D2; t += blockDim.x) sw[OFF_NB1 + t] = nb1[t];
    for (int t = threadIdx.x; t < D2 * D3; t += blockDim.x) {
        int j = t / D3, k = t % D3;
        sw[OFF_NW2 + j * D3P + k] = nw2[t];
    }
    for (int t = threadIdx.x; t < D3; t += blockDim.x) sw[OFF_NB2 + t] = nb2[t];
    __syncthreads();

    int e = blockIdx.x * blockDim.x + threadIdx.x;
    if (e >= E) return;

    int r = row[e];
    int c = col[e];

    float in9[9];
    in9[0] = x[3 * r + 0]; in9[1] = x[3 * r + 1]; in9[2] = x[3 * r + 2];
    in9[3] = x[3 * c + 0]; in9[4] = x[3 * c + 1]; in9[5] = x[3 * c + 2];
    in9[6] = ea[3 * e + 0]; in9[7] = ea[3 * e + 1]; in9[8] = ea[3 * e + 2];

    // ---- edge MLP layer 1: h = relu(eb1 + in9 @ ew1) ----
    float h[D2P];
    {
        const float4* bv = reinterpret_cast<const float4*>(&sw[OFF_EB1]);
        #pragma unroll
        for (int jj = 0; jj < D2P / 4; ++jj) {
            float4 v = bv[jj];
            h[4 * jj + 0] = v.x; h[4 * jj + 1] = v.y;
            h[4 * jj + 2] = v.z; h[4 * jj + 3] = v.w;
        }
    }
    for (int i = 0; i < 9; ++i) {
        float xi = in9[i];
        const float4* wv = reinterpret_cast<const float4*>(&sw[OFF_EW1 + i * D2P]);
        #pragma unroll
        for (int jj = 0; jj < D2P / 4; ++jj) {
            float4 w = wv[jj];
            h[4 * jj + 0] += xi * w.x; h[4 * jj + 1] += xi * w.y;
            h[4 * jj + 2] += xi * w.z; h[4 * jj + 3] += xi * w.w;
        }
    }
    #pragma unroll
    for (int j = 0; j < D2; ++j) h[j] = fmaxf(h[j], 0.0f);

    // ---- edge MLP layer 2: e2 = eb2 + h @ ew2 ----
    float e2[D3P];
    {
        const float4* bv = reinterpret_cast<const float4*>(&sw[OFF_EB2]);
        #pragma unroll
        for (int kk = 0; kk < D3P / 4; ++kk) {
            float4 v = bv[kk];
            e2[4 * kk + 0] = v.x; e2[4 * kk + 1] = v.y;
            e2[4 * kk + 2] = v.z; e2[4 * kk + 3] = v.w;
        }
    }
    for (int j = 0; j < D2; ++j) {
        float hj = h[j];
        const float4* wv = reinterpret_cast<const float4*>(&sw[OFF_EW2 + j * D3P]);
        #pragma unroll
        for (int kk = 0; kk < D3P / 4; ++kk) {
            float4 w = wv[kk];
            e2[4 * kk + 0] += hj * w.x; e2[4 * kk + 1] += hj * w.y;
            e2[4 * kk + 2] += hj * w.z; e2[4 * kk + 3] += hj * w.w;
        }
    }

    // ---- node MLP layer 1: h2 = relu(nb1 + [x[col], e2] @ nw1) ----
    float h2[D2P];
    {
        const float4* bv = reinterpret_cast<const float4*>(&sw[OFF_NB1]);
        #pragma unroll
        for (int jj = 0; jj < D2P / 4; ++jj) {
            float4 v = bv[jj];
            h2[4 * jj + 0] = v.x; h2[4 * jj + 1] = v.y;
            h2[4 * jj + 2] = v.z; h2[4 * jj + 3] = v.w;
        }
    }
    #pragma unroll
    for (int i = 0; i < 18; ++i) {
        float xi = (i < 3) ? in9[3 + i] : e2[i - 3];
        const float4* wv = reinterpret_cast<const float4*>(&sw[OFF_NW1 + i * D2P]);
        #pragma unroll
        for (int jj = 0; jj < D2P / 4; ++jj) {
            float4 w = wv[jj];
            h2[4 * jj + 0] += xi * w.x; h2[4 * jj + 1] += xi * w.y;
            h2[4 * jj + 2] += xi * w.z; h2[4 * jj + 3] += xi * w.w;
        }
    }
    #pragma unroll
    for (int j = 0; j < D2; ++j) h2[j] = fmaxf(h2[j], 0.0f);

    // ---- node MLP layer 2: o = nb2 + h2 @ nw2 ----
    float o[D3P];
    {
        const float4* bv = reinterpret_cast<const float4*>(&sw[OFF_NB2]);
        #pragma unroll
        for (int kk = 0; kk < D3P / 4; ++kk) {
            float4 v = bv[kk];
            o[4 * kk + 0] = v.x; o[4 * kk + 1] = v.y;
            o[4 * kk + 2] = v.z; o[4 * kk + 3] = v.w;
        }
    }
    for (int j = 0; j < D2; ++j) {
        float hj = h2[j];
        const float4* wv = reinterpret_cast<const float4*>(&sw[OFF_NW2 + j * D3P]);
        #pragma unroll
        for (int kk = 0; kk < D3P / 4; ++kk) {
            float4 w = wv[kk];
            o[4 * kk + 0] += hj * w.x; o[4 * kk + 1] += hj * w.y;
            o[4 * kk + 2] += hj * w.z; o[4 * kk + 3] += hj * w.w;
        }
    }

    // ---- scatter: x2sum[row] += o, cnt[row] += 1 ----
    float* dst = &g_x2sum[r * D3];
    #pragma unroll
    for (int k = 0; k < D3; ++k) atomicAdd(dst + k, o[k]);
    atomicAdd(&g_cnt[r], 1.0f);
}

// ---------------- node kernel: normalize + per-graph scatter ----------------
__global__ void node_kernel(const int* __restrict__ batch, int N) {
    int n = blockIdx.x * blockDim.x + threadIdx.x;
    if (n >= N) return;

    float cntv = g_cnt[n];
    float inv = 1.0f / fmaxf(cntv, 1.0f);
    int b = batch[n];

    #pragma unroll
    for (int k = 0; k < D3; ++k) {
        float v = g_x2sum[n * D3 + k] * inv;          // x2[n][k]
        atomicAdd(&g_gsum[b * D3 + k], v);            // for per-graph mean(x2)
        atomicAdd(&g_zsum[b * D3 + k], fmaxf(v, 0.0f)); // for readout sum relu(x2)
    }
    atomicAdd(&g_gcnt[b], 1.0f);
}

// ---------------- final kernel: global MLP + readout + head ----------------
__global__ void final_kernel(
    const float* __restrict__ u,
    const float* __restrict__ gw1, const float* __restrict__ gb1,
    const float* __restrict__ gw2, const float* __restrict__ gb2,
    const float* __restrict__ fc1w, const float* __restrict__ fc1b,
    const float* __restrict__ bng, const float* __restrict__ bnb,
    const float* __restrict__ fc2w, const float* __restrict__ fc2b,
    float* __restrict__ out, int B)
{
    int b = blockIdx.x * blockDim.x + threadIdx.x;
    if (b >= B) return;

    float cnt = g_gcnt[b];
    float invc = 1.0f / fmaxf(cnt, 1.0f);

    // input to global MLP: [u[b], mean_per_graph(x2)]
    float in16[16];
    in16[0] = u[b];
    #pragma unroll
    for (int k = 0; k < D3; ++k) in16[1 + k] = g_gsum[b * D3 + k] * invc;

    // global MLP layer 1 (16 -> 50)
    float hg[D2];
    #pragma unroll
    for (int j = 0; j < D2; ++j) hg[j] = gb1[j];
    #pragma unroll
    for (int i = 0; i < 16; ++i) {
        float xi = in16[i];
        #pragma unroll
        for (int j = 0; j < D2; ++j) hg[j] += xi * gw1[i * D2 + j];
    }
    #pragma unroll
    for (int j = 0; j < D2; ++j) hg[j] = fmaxf(hg[j], 0.0f);

    // global MLP layer 2 (50 -> 15): u2
    float u2[D3];
    #pragma unroll
    for (int k = 0; k < D3; ++k) u2[k] = gb2[k];
    #pragma unroll
    for (int j = 0; j < D2; ++j) {
        float hj = hg[j];
        #pragma unroll
        for (int k = 0; k < D3; ++k) u2[k] += hj * gw2[j * D3 + k];
    }

    // readout mean: (sum relu(x2 nodes) + relu(u2)) / (count + 1)
    float invg = 1.0f / (cnt + 1.0f);
    float g[D3];
    #pragma unroll
    for (int k = 0; k < D3; ++k)
        g[k] = (g_zsum[b * D3 + k] + fmaxf(u2[k], 0.0f)) * invg;

    // fc1 (15 -> 10)
    float h1[D5];
    #pragma unroll
    for (int m = 0; m < D5; ++m) h1[m] = fc1b[m];
    #pragma unroll
    for (int k = 0; k < D3; ++k) {
        float gk = g[k];
        #pragma unroll
        for (int m = 0; m < D5; ++m) h1[m] += gk * fc1w[k * D5 + m];
    }

    // BatchNorm1d (eval, running mean=0, var=1) + relu
    float rs = rsqrtf(1.0f + 1e-5f);
    #pragma unroll
    for (int m = 0; m < D5; ++m)
        h1[m] = fmaxf(h1[m] * (bng[m] * rs) + bnb[m], 0.0f);

    // fc2 (10 -> 6)
    float lg[NC];
    #pragma unroll
    for (int q = 0; q < NC; ++q) lg[q] = fc2b[q];
    #pragma unroll
    for (int m = 0; m < D5; ++m) {
        float hm = h1[m];
        #pragma unroll
        for (int q = 0; q < NC; ++q) lg[q] += hm * fc2w[m * NC + q];
    }

    // log_softmax
    float mx = lg[0];
    #pragma unroll
    for (int q = 1; q < NC; ++q) mx = fmaxf(mx, lg[q]);
    float s = 0.0f;
    #pragma unroll
    for (int q = 0; q < NC; ++q) s += expf(lg[q] - mx);
    float lse = mx + logf(s);
    #pragma unroll
    for (int q = 0; q < NC; ++q) out[b * NC + q] = lg[q] - lse;
}

// ---------------- launch ----------------
extern "C" void kernel_launch(void* const* d_in, const int* in_sizes, int n_in,
                              void* d_out, int out_size) {
    const float* x     = (const float*)d_in[0];
    const int*   ei    = (const int*)d_in[1];
    const float* ea    = (const float*)d_in[2];
    const float* u     = (const float*)d_in[3];
    const int*   batch = (const int*)d_in[4];
    const float* ew1   = (const float*)d_in[5];
    const float* eb1   = (const float*)d_in[6];
    const float* ew2   = (const float*)d_in[7];
    const float* eb2   = (const float*)d_in[8];
    const float* nw1   = (const float*)d_in[9];
    const float* nb1   = (const float*)d_in[10];
    const float* nw2   = (const float*)d_in[11];
    const float* nb2   = (const float*)d_in[12];
    const float* gw1   = (const float*)d_in[13];
    const float* gb1   = (const float*)d_in[14];
    const float* gw2   = (const float*)d_in[15];
    const float* gb2   = (const float*)d_in[16];
    const float* fc1w  = (const float*)d_in[17];
    const float* fc1b  = (const float*)d_in[18];
    const float* bng   = (const float*)d_in[19];
    const float* bnb   = (const float*)d_in[20];
    const float* fc2w  = (const float*)d_in[21];
    const float* fc2b  = (const float*)d_in[22];
    float* out = (float*)d_out;

    int N = in_sizes[0] / 3;   // nodes
    int E = in_sizes[1] / 2;   // edges
    int B = in_sizes[3];       // graphs (u is [B,1])

    const int* row = ei;
    const int* col = ei + E;

    zero_kernel<<<1024, 256>>>();
    edge_kernel<<<(E + 255) / 256, 256>>>(x, row, col, ea,
                                          ew1, eb1, ew2, eb2,
                                          nw1, nb1, nw2, nb2, E);
    node_kernel<<<(N + 255) / 256, 256>>>(batch, N);
    final_kernel<<<1, 256>>>(u, gw1, gb1, gw2, gb2,
                             fc1w, fc1b, bng, bnb, fc2w, fc2b, out, B);
}

// round 5
// speedup vs baseline: 1.3429x; 1.3429x over previous
#include <cuda_runtime.h>
#include <math.h>

// Problem dims (fixed by setup_inputs)
#define MAXN 100000
#define MAXB 256
#define D2 50
#define D3 15
#define D2P 52   // D2 padded to multiple of 4
#define D3P 16   // D3 padded to multiple of 4
#define D5 10
#define NC 6

// ---------------- device scratch (no allocations allowed) ----------------
// per-node record: 15 accum floats + count in slot 15 (16 floats = 64B)
__device__ __align__(16) float g_x2sum[MAXN * 16];

// ---------------- packed f32x2 helpers ----------------
__device__ __forceinline__ unsigned long long pack2(float a, float b) {
    unsigned long long r;
    asm("mov.b64 %0, {%1, %2};" : "=l"(r) : "f"(a), "f"(b));
    return r;
}
__device__ __forceinline__ void unpack2(unsigned long long v, float& a, float& b) {
    asm("mov.b64 {%0, %1}, %2;" : "=f"(a), "=f"(b) : "l"(v));
}
__device__ __forceinline__ void ffma2(unsigned long long& acc,
                                      unsigned long long a, unsigned long long b) {
    asm("fma.rn.f32x2 %0, %1, %2, %0;" : "+l"(acc) : "l"(a), "l"(b));
}
__device__ __forceinline__ void red4(float* p, float a, float b, float c, float d) {
    asm volatile("red.global.add.v4.f32 [%0], {%1, %2, %3, %4};"
                 :: "l"(p), "f"(a), "f"(b), "f"(c), "f"(d) : "memory");
}

// ---------------- zero accumulators ----------------
__global__ void zero_kernel(int N) {
    int tid = blockIdx.x * blockDim.x + threadIdx.x;
    int stride = gridDim.x * blockDim.x;
    int total = N * 4;  // in float4 units
    float4 z = make_float4(0.f, 0.f, 0.f, 0.f);
    float4* p = reinterpret_cast<float4*>(g_x2sum);
    for (int t = tid; t < total; t += stride) p[t] = z;
}

// ---------------- shared-memory layout for edge kernel weights ----------------
// all offsets multiples of 4 floats (16B) -> float4/ulonglong2 LDS works
#define OFF_EW1 0                       // [9][52]
#define OFF_EB1 (OFF_EW1 + 9 * D2P)     // 468
#define OFF_EW2 (OFF_EB1 + D2P)         // 520, [50][16]
#define OFF_EB2 (OFF_EW2 + D2 * D3P)    // 1320
#define OFF_NW1 (OFF_EB2 + D3P)         // 1336, [18][52]
#define OFF_NB1 (OFF_NW1 + 18 * D2P)    // 2272
#define OFF_NW2 (OFF_NB1 + D2P)         // 2324, [50][16]
#define OFF_NB2 (OFF_NW2 + D2 * D3P)    // 3124
#define SW_TOTAL (OFF_NB2 + D3P)        // 3140 floats

// ---------------- edge kernel: edge MLP + node MLP + vector-red scatter -----
__global__ void __launch_bounds__(256)
edge_kernel(
    const float* __restrict__ x,
    const int* __restrict__ row,
    const int* __restrict__ col,
    const float* __restrict__ ea,
    const float* __restrict__ ew1, const float* __restrict__ eb1,
    const float* __restrict__ ew2, const float* __restrict__ eb2,
    const float* __restrict__ nw1, const float* __restrict__ nb1,
    const float* __restrict__ nw2, const float* __restrict__ nb2,
    int E)
{
    __shared__ __align__(16) float sw[SW_TOTAL];

    for (int t = threadIdx.x; t < SW_TOTAL; t += blockDim.x) sw[t] = 0.0f;
    __syncthreads();
    for (int t = threadIdx.x; t < 9 * D2; t += blockDim.x) {
        int i = t / D2, j = t % D2;
        sw[OFF_EW1 + i * D2P + j] = ew1[t];
    }
    for (int t = threadIdx.x; t < D2; t += blockDim.x) sw[OFF_EB1 + t] = eb1[t];
    for (int t = threadIdx.x; t < D2 * D3; t += blockDim.x) {
        int j = t / D3, k = t % D3;
        sw[OFF_EW2 + j * D3P + k] = ew2[t];
    }
    for (int t = threadIdx.x; t < D3; t += blockDim.x) sw[OFF_EB2 + t] = eb2[t];
    for (int t = threadIdx.x; t < 18 * D2; t += blockDim.x) {
        int i = t / D2, j = t % D2;
        sw[OFF_NW1 + i * D2P + j] = nw1[t];
    }
    for (int t = threadIdx.x; t < D2; t += blockDim.x) sw[OFF_NB1 + t] = nb1[t];
    for (int t = threadIdx.x; t < D2 * D3; t += blockDim.x) {
        int j = t / D3, k = t % D3;
        sw[OFF_NW2 + j * D3P + k] = nw2[t];
    }
    for (int t = threadIdx.x; t < D3; t += blockDim.x) sw[OFF_NB2 + t] = nb2[t];
    __syncthreads();

    int e = blockIdx.x * blockDim.x + threadIdx.x;
    if (e >= E) return;

    const unsigned long long* swu = reinterpret_cast<const unsigned long long*>(sw);

    int r = row[e];
    int c = col[e];

    float in9[9];
    in9[0] = x[3 * r + 0]; in9[1] = x[3 * r + 1]; in9[2] = x[3 * r + 2];
    in9[3] = x[3 * c + 0]; in9[4] = x[3 * c + 1]; in9[5] = x[3 * c + 2];
    in9[6] = ea[3 * e + 0]; in9[7] = ea[3 * e + 1]; in9[8] = ea[3 * e + 2];

    // ---- edge MLP layer 1: h = relu(eb1 + in9 @ ew1) ----  (26 packed pairs)
    unsigned long long h[26];
    #pragma unroll
    for (int jj = 0; jj < 26; ++jj) h[jj] = swu[OFF_EB1 / 2 + jj];
    #pragma unroll
    for (int i = 0; i < 9; ++i) {
        unsigned long long xi2 = pack2(in9[i], in9[i]);
        const ulonglong2* wv = reinterpret_cast<const ulonglong2*>(
            &sw[OFF_EW1 + i * D2P]);
        #pragma unroll
        for (int q = 0; q < 13; ++q) {
            ulonglong2 w = wv[q];
            ffma2(h[2 * q + 0], xi2, w.x);
            ffma2(h[2 * q + 1], xi2, w.y);
        }
    }
    float hf[52];
    #pragma unroll
    for (int jj = 0; jj < 26; ++jj) unpack2(h[jj], hf[2 * jj], hf[2 * jj + 1]);
    #pragma unroll
    for (int j = 0; j < D2; ++j) hf[j] = fmaxf(hf[j], 0.0f);

    // ---- edge MLP layer 2: e2 = eb2 + h @ ew2 ----  (8 packed pairs)
    unsigned long long e2[8];
    #pragma unroll
    for (int kk = 0; kk < 8; ++kk) e2[kk] = swu[OFF_EB2 / 2 + kk];
    #pragma unroll
    for (int j = 0; j < D2; ++j) {
        unsigned long long hj2 = pack2(hf[j], hf[j]);
        const ulonglong2* wv = reinterpret_cast<const ulonglong2*>(
            &sw[OFF_EW2 + j * D3P]);
        #pragma unroll
        for (int q = 0; q < 4; ++q) {
            ulonglong2 w = wv[q];
            ffma2(e2[2 * q + 0], hj2, w.x);
            ffma2(e2[2 * q + 1], hj2, w.y);
        }
    }
    float e2f[16];
    #pragma unroll
    for (int kk = 0; kk < 8; ++kk) unpack2(e2[kk], e2f[2 * kk], e2f[2 * kk + 1]);

    // ---- node MLP layer 1: h2 = relu(nb1 + [x[col], e2] @ nw1) ----
    unsigned long long h2[26];
    #pragma unroll
    for (int jj = 0; jj < 26; ++jj) h2[jj] = swu[OFF_NB1 / 2 + jj];
    #pragma unroll
    for (int i = 0; i < 18; ++i) {
        float xi = (i < 3) ? in9[3 + i] : e2f[i - 3];
        unsigned long long xi2 = pack2(xi, xi);
        const ulonglong2* wv = reinterpret_cast<const ulonglong2*>(
            &sw[OFF_NW1 + i * D2P]);
        #pragma unroll
        for (int q = 0; q < 13; ++q) {
            ulonglong2 w = wv[q];
            ffma2(h2[2 * q + 0], xi2, w.x);
            ffma2(h2[2 * q + 1], xi2, w.y);
        }
    }
    float h2f[52];
    #pragma unroll
    for (int jj = 0; jj < 26; ++jj) unpack2(h2[jj], h2f[2 * jj], h2f[2 * jj + 1]);
    #pragma unroll
    for (int j = 0; j < D2; ++j) h2f[j] = fmaxf(h2f[j], 0.0f);

    // ---- node MLP layer 2: o = nb2 + h2 @ nw2 ----
    unsigned long long o[8];
    #pragma unroll
    for (int kk = 0; kk < 8; ++kk) o[kk] = swu[OFF_NB2 / 2 + kk];
    #pragma unroll
    for (int j = 0; j < D2; ++j) {
        unsigned long long hj2 = pack2(h2f[j], h2f[j]);
        const ulonglong2* wv = reinterpret_cast<const ulonglong2*>(
            &sw[OFF_NW2 + j * D3P]);
        #pragma unroll
        for (int q = 0; q < 4; ++q) {
            ulonglong2 w = wv[q];
            ffma2(o[2 * q + 0], hj2, w.x);
            ffma2(o[2 * q + 1], hj2, w.y);
        }
    }
    float of[16];
    #pragma unroll
    for (int kk = 0; kk < 8; ++kk) unpack2(o[kk], of[2 * kk], of[2 * kk + 1]);

    // ---- scatter: x2sum[row] += o (15 vals), count in slot 15 ----
    float* dst = &g_x2sum[(size_t)r * 16];
    red4(dst + 0,  of[0],  of[1],  of[2],  of[3]);
    red4(dst + 4,  of[4],  of[5],  of[6],  of[7]);
    red4(dst + 8,  of[8],  of[9],  of[10], of[11]);
    red4(dst + 12, of[12], of[13], of[14], 1.0f);
}

// ---------------- graph kernel: per-graph reduce + global MLP + head --------
// one block per graph; batch is sorted -> boundaries by binary search.
#define SG_GW1 0
#define SG_GB1 (SG_GW1 + 16 * D2)      // 800
#define SG_GW2 (SG_GB1 + D2)           // 850
#define SG_GB2 (SG_GW2 + D2 * D3)      // 1600
#define SG_F1W (SG_GB2 + D3)           // 1615
#define SG_F1B (SG_F1W + D3 * D5)      // 1765
#define SG_BNG (SG_F1B + D5)           // 1775
#define SG_BNB (SG_BNG + D5)           // 1785
#define SG_F2W (SG_BNB + D5)           // 1795
#define SG_F2B (SG_F2W + D5 * NC)      // 1855
#define SG_TOTAL (SG_F2B + NC)         // 1861

__device__ __forceinline__ int lbound(const int* a, int n, int key) {
    int lo = 0, hi = n;
    while (lo < hi) { int m = (lo + hi) >> 1; if (a[m] < key) lo = m + 1; else hi = m; }
    return lo;
}

__global__ void __launch_bounds__(256)
graph_kernel(
    const int* __restrict__ batch,
    const float* __restrict__ u,
    const float* __restrict__ gw1, const float* __restrict__ gb1,
    const float* __restrict__ gw2, const float* __restrict__ gb2,
    const float* __restrict__ fc1w, const float* __restrict__ fc1b,
    const float* __restrict__ bng, const float* __restrict__ bnb,
    const float* __restrict__ fc2w, const float* __restrict__ fc2b,
    float* __restrict__ out, int N)
{
    __shared__ float swt[SG_TOTAL];
    __shared__ float sred[8][30];
    __shared__ int sse[2];

    int tid = threadIdx.x;
    // cooperative weight staging
    for (int t = tid; t < 16 * D2; t += blockDim.x) swt[SG_GW1 + t] = gw1[t];
    for (int t = tid; t < D2; t += blockDim.x) swt[SG_GB1 + t] = gb1[t];
    for (int t = tid; t < D2 * D3; t += blockDim.x) swt[SG_GW2 + t] = gw2[t];
    for (int t = tid; t < D3; t += blockDim.x) swt[SG_GB2 + t] = gb2[t];
    for (int t = tid; t < D3 * D5; t += blockDim.x) swt[SG_F1W + t] = fc1w[t];
    for (int t = tid; t < D5; t += blockDim.x) {
        swt[SG_F1B + t] = fc1b[t];
        swt[SG_BNG + t] = bng[t];
        swt[SG_BNB + t] = bnb[t];
    }
    for (int t = tid; t < D5 * NC; t += blockDim.x) swt[SG_F2W + t] = fc2w[t];
    for (int t = tid; t < NC; t += blockDim.x) swt[SG_F2B + t] = fc2b[t];

    int b = blockIdx.x;
    if (tid == 0) {
        sse[0] = lbound(batch, N, b);
        sse[1] = lbound(batch, N, b + 1);
    }
    __syncthreads();
    int s = sse[0], epos = sse[1];
    int nnodes = epos - s;

    // accumulate per-thread partials of sum(x2) and sum(relu(x2))
    float acc[30];
    #pragma unroll
    for (int k = 0; k < 30; ++k) acc[k] = 0.0f;

    for (int n = s + tid; n < epos; n += blockDim.x) {
        const float4* p = reinterpret_cast<const float4*>(&g_x2sum[(size_t)n * 16]);
        float4 a0 = p[0], a1 = p[1], a2 = p[2], a3 = p[3];
        float vv[15] = { a0.x, a0.y, a0.z, a0.w, a1.x, a1.y, a1.z, a1.w,
                         a2.x, a2.y, a2.z, a2.w, a3.x, a3.y, a3.z };
        float cnt = a3.w;
        float inv = 1.0f / fmaxf(cnt, 1.0f);
        #pragma unroll
        for (int k = 0; k < 15; ++k) {
            float t = vv[k] * inv;
            acc[k] += t;
            acc[15 + k] += fmaxf(t, 0.0f);
        }
    }

    // warp reduce then cross-warp via shared
    #pragma unroll
    for (int k = 0; k < 30; ++k) {
        float v = acc[k];
        #pragma unroll
        for (int off = 16; off > 0; off >>= 1)
            v += __shfl_down_sync(0xFFFFFFFF, v, off);
        acc[k] = v;
    }
    int wid = tid >> 5, lid = tid & 31;
    if (lid == 0) {
        #pragma unroll
        for (int k = 0; k < 30; ++k) sred[wid][k] = acc[k];
    }
    __syncthreads();

    if (tid == 0) {
        float gsum[15], zsum[15];
        #pragma unroll
        for (int k = 0; k < 15; ++k) { gsum[k] = 0.0f; zsum[k] = 0.0f; }
        for (int w = 0; w < (int)(blockDim.x >> 5); ++w) {
            #pragma unroll
            for (int k = 0; k < 15; ++k) {
                gsum[k] += sred[w][k];
                zsum[k] += sred[w][15 + k];
            }
        }

        float cntf = (float)nnodes;
        float invc = 1.0f / fmaxf(cntf, 1.0f);

        float in16[16];
        in16[0] = u[b];
        #pragma unroll
        for (int k = 0; k < 15; ++k) in16[1 + k] = gsum[k] * invc;

        // global MLP layer 1 (16 -> 50)
        float hg[D2];
        #pragma unroll
        for (int j = 0; j < D2; ++j) hg[j] = swt[SG_GB1 + j];
        #pragma unroll
        for (int i = 0; i < 16; ++i) {
            float xi = in16[i];
            #pragma unroll
            for (int j = 0; j < D2; ++j) hg[j] += xi * swt[SG_GW1 + i * D2 + j];
        }
        #pragma unroll
        for (int j = 0; j < D2; ++j) hg[j] = fmaxf(hg[j], 0.0f);

        // global MLP layer 2 (50 -> 15)
        float u2[D3];
        #pragma unroll
        for (int k = 0; k < D3; ++k) u2[k] = swt[SG_GB2 + k];
        #pragma unroll
        for (int j = 0; j < D2; ++j) {
            float hj = hg[j];
            #pragma unroll
            for (int k = 0; k < D3; ++k) u2[k] += hj * swt[SG_GW2 + j * D3 + k];
        }

        // readout mean: (sum relu(x2 nodes) + relu(u2)) / (nnodes + 1)
        float invg = 1.0f / (cntf + 1.0f);
        float g[D3];
        #pragma unroll
        for (int k = 0; k < D3; ++k)
            g[k] = (zsum[k] + fmaxf(u2[k], 0.0f)) * invg;

        // fc1 (15 -> 10)
        float h1[D5];
        #pragma unroll
        for (int m = 0; m < D5; ++m) h1[m] = swt[SG_F1B + m];
        #pragma unroll
        for (int k = 0; k < D3; ++k) {
            float gk = g[k];
            #pragma unroll
            for (int m = 0; m < D5; ++m) h1[m] += gk * swt[SG_F1W + k * D5 + m];
        }

        // BatchNorm1d (eval, mean=0, var=1) + relu
        float rs = rsqrtf(1.0f + 1e-5f);
        #pragma unroll
        for (int m = 0; m < D5; ++m)
            h1[m] = fmaxf(h1[m] * (swt[SG_BNG + m] * rs) + swt[SG_BNB + m], 0.0f);

        // fc2 (10 -> 6)
        float lg[NC];
        #pragma unroll
        for (int q = 0; q < NC; ++q) lg[q] = swt[SG_F2B + q];
        #pragma unroll
        for (int m = 0; m < D5; ++m) {
            float hm = h1[m];
            #pragma unroll
            for (int q = 0; q < NC; ++q) lg[q] += hm * swt[SG_F2W + m * NC + q];
        }

        // log_softmax
        float mx = lg[0];
        #pragma unroll
        for (int q = 1; q < NC; ++q) mx = fmaxf(mx, lg[q]);
        float ssum = 0.0f;
        #pragma unroll
        for (int q = 0; q < NC; ++q) ssum += expf(lg[q] - mx);
        float lse = mx + logf(ssum);
        #pragma unroll
        for (int q = 0; q < NC; ++q) out[b * NC + q] = lg[q] - lse;
    }
}

// ---------------- launch ----------------
extern "C" void kernel_launch(void* const* d_in, const int* in_sizes, int n_in,
                              void* d_out, int out_size) {
    const float* x     = (const float*)d_in[0];
    const int*   ei    = (const int*)d_in[1];
    const float* ea    = (const float*)d_in[2];
    const float* u     = (const float*)d_in[3];
    const int*   batch = (const int*)d_in[4];
    const float* ew1   = (const float*)d_in[5];
    const float* eb1   = (const float*)d_in[6];
    const float* ew2   = (const float*)d_in[7];
    const float* eb2   = (const float*)d_in[8];
    const float* nw1   = (const float*)d_in[9];
    const float* nb1   = (const float*)d_in[10];
    const float* nw2   = (const float*)d_in[11];
    const float* nb2   = (const float*)d_in[12];
    const float* gw1   = (const float*)d_in[13];
    const float* gb1   = (const float*)d_in[14];
    const float* gw2   = (const float*)d_in[15];
    const float* gb2   = (const float*)d_in[16];
    const float* fc1w  = (const float*)d_in[17];
    const float* fc1b  = (const float*)d_in[18];
    const float* bng   = (const float*)d_in[19];
    const float* bnb   = (const float*)d_in[20];
    const float* fc2w  = (const float*)d_in[21];
    const float* fc2b  = (const float*)d_in[22];
    float* out = (float*)d_out;

    int N = in_sizes[0] / 3;   // nodes
    int E = in_sizes[1] / 2;   // edges
    int B = in_sizes[3];       // graphs (u is [B,1])

    const int* row = ei;
    const int* col = ei + E;

    zero_kernel<<<512, 256>>>(N);
    edge_kernel<<<(E + 255) / 256, 256>>>(x, row, col, ea,
                                          ew1, eb1, ew2, eb2,
                                          nw1, nb1, nw2, nb2, E);
    graph_kernel<<<B, 256>>>(batch, u,
                             gw1, gb1, gw2, gb2,
                             fc1w, fc1b, bng, bnb, fc2w, fc2b, out, N);
}

// round 6
// speedup vs baseline: 1.8148x; 1.3514x over previous
#include <cuda_runtime.h>
#include <math.h>

// Problem dims (fixed by setup_inputs)
#define MAXN 100000
#define MAXB 256
#define D2 50
#define D3 15
#define D2P 52
#define D5 10
#define NC 6

// ---------------- device scratch ----------------
// per-node record: 15 accum floats + count in slot 15 (16 floats = 64B)
__device__ __align__(16) float g_x2sum[MAXN * 16];

// ---------------- packed f32x2 helpers ----------------
__device__ __forceinline__ unsigned long long pack2(float a, float b) {
    unsigned long long r;
    asm("mov.b64 %0, {%1, %2};" : "=l"(r) : "f"(a), "f"(b));
    return r;
}
__device__ __forceinline__ void unpack2(unsigned long long v, float& a, float& b) {
    asm("mov.b64 {%0, %1}, %2;" : "=f"(a), "=f"(b) : "l"(v));
}
__device__ __forceinline__ void ffma2(unsigned long long& acc,
                                      unsigned long long a, unsigned long long b) {
    asm("fma.rn.f32x2 %0, %1, %2, %0;" : "+l"(acc) : "l"(a), "l"(b));
}
__device__ __forceinline__ void red4(float* p, float a, float b, float c, float d) {
    asm volatile("red.global.add.v4.f32 [%0], {%1, %2, %3, %4};"
                 :: "l"(p), "f"(a), "f"(b), "f"(c), "f"(d) : "memory");
}

// ---------------- zero accumulators ----------------
__global__ void zero_kernel(int N) {
    int tid = blockIdx.x * blockDim.x + threadIdx.x;
    int stride = gridDim.x * blockDim.x;
    int total = N * 4;  // float4 units
    float4 z = make_float4(0.f, 0.f, 0.f, 0.f);
    float4* p = reinterpret_cast<float4*>(g_x2sum);
    for (int t = tid; t < total; t += stride) p[t] = z;
}

// ---------------- SMEM weight layout (floats, all 16B-aligned offsets) -----
// layer-1 weights: [in][52] padded rows (broadcast multiplicand scheme)
// layer-2 weights: j-pair transposed: [16 outs][52] where float (k*52 + j)
//                  holds w2[j][k]; pairs (j,j+1) feed fma.f32x2 directly.
#define OFF_EW1  0                        // [9][52]  = 468
#define OFF_EB1  468                      // [52]
#define OFF_EW2P 520                      // [16][52] = 832
#define OFF_EB2  1352                     // [16]
#define OFF_NW1  1368                     // [18][52] = 936
#define OFF_NB1  2304                     // [52]
#define OFF_NW2P 2356                     // [16][52] = 832
#define OFF_NB2  3188                     // [16]
#define SW_TOTAL 3204

// ---------------- edge kernel: 2 edges/thread, shared weight LDS ----------
__global__ void __launch_bounds__(128, 3)
edge_kernel(
    const float* __restrict__ x,
    const int* __restrict__ row,
    const int* __restrict__ col,
    const float* __restrict__ ea,
    const float* __restrict__ ew1, const float* __restrict__ eb1,
    const float* __restrict__ ew2, const float* __restrict__ eb2,
    const float* __restrict__ nw1, const float* __restrict__ nb1,
    const float* __restrict__ nw2, const float* __restrict__ nb2,
    int p_start, int p_end, int E)
{
    __shared__ __align__(16) float sw[SW_TOTAL];

    for (int t = threadIdx.x; t < SW_TOTAL; t += blockDim.x) sw[t] = 0.0f;
    __syncthreads();
    // layer-1 weights, padded row stride 52
    for (int t = threadIdx.x; t < 9 * D2; t += blockDim.x) {
        int i = t / D2, j = t % D2;
        sw[OFF_EW1 + i * D2P + j] = ew1[t];
    }
    for (int t = threadIdx.x; t < D2; t += blockDim.x) sw[OFF_EB1 + t] = eb1[t];
    // layer-2 weights, j-pair transposed: dst float = k*52 + j
    for (int t = threadIdx.x; t < D2 * D3; t += blockDim.x) {
        int j = t / D3, k = t % D3;
        sw[OFF_EW2P + k * D2P + j] = ew2[t];
    }
    for (int t = threadIdx.x; t < D3; t += blockDim.x) sw[OFF_EB2 + t] = eb2[t];
    for (int t = threadIdx.x; t < 18 * D2; t += blockDim.x) {
        int i = t / D2, j = t % D2;
        sw[OFF_NW1 + i * D2P + j] = nw1[t];
    }
    for (int t = threadIdx.x; t < D2; t += blockDim.x) sw[OFF_NB1 + t] = nb1[t];
    for (int t = threadIdx.x; t < D2 * D3; t += blockDim.x) {
        int j = t / D3, k = t % D3;
        sw[OFF_NW2P + k * D2P + j] = nw2[t];
    }
    for (int t = threadIdx.x; t < D3; t += blockDim.x) sw[OFF_NB2 + t] = nb2[t];
    __syncthreads();

    int p = p_start + blockIdx.x * blockDim.x + threadIdx.x;
    if (p >= p_end) return;

    int e0 = 2 * p;
    int e1 = 2 * p + 1;
    bool validB = (e1 < E);
    int e1c = validB ? e1 : (E - 1);

    int rA = row[e0], cA = col[e0];
    int rB = row[e1c], cB = col[e1c];

    float inA[9], inB[9];
    inA[0] = x[3 * rA + 0]; inA[1] = x[3 * rA + 1]; inA[2] = x[3 * rA + 2];
    inA[3] = x[3 * cA + 0]; inA[4] = x[3 * cA + 1]; inA[5] = x[3 * cA + 2];
    inA[6] = ea[3 * e0 + 0]; inA[7] = ea[3 * e0 + 1]; inA[8] = ea[3 * e0 + 2];
    inB[0] = x[3 * rB + 0]; inB[1] = x[3 * rB + 1]; inB[2] = x[3 * rB + 2];
    inB[3] = x[3 * cB + 0]; inB[4] = x[3 * cB + 1]; inB[5] = x[3 * cB + 2];
    inB[6] = ea[3 * e1c + 0]; inB[7] = ea[3 * e1c + 1]; inB[8] = ea[3 * e1c + 2];

    // ==== edge MLP layer 1: h = relu(eb1 + in9 @ ew1), packed along outputs
    unsigned long long hA[26], hB[26];
    {
        const ulonglong2* bv = reinterpret_cast<const ulonglong2*>(&sw[OFF_EB1]);
        #pragma unroll
        for (int q2 = 0; q2 < 13; ++q2) {
            ulonglong2 b = bv[q2];
            hA[2 * q2] = b.x; hA[2 * q2 + 1] = b.y;
            hB[2 * q2] = b.x; hB[2 * q2 + 1] = b.y;
        }
    }
    #pragma unroll
    for (int i = 0; i < 9; ++i) {
        unsigned long long pa = pack2(inA[i], inA[i]);
        unsigned long long pb = pack2(inB[i], inB[i]);
        const ulonglong2* wv = reinterpret_cast<const ulonglong2*>(&sw[OFF_EW1 + i * D2P]);
        #pragma unroll
        for (int q2 = 0; q2 < 13; ++q2) {
            ulonglong2 w = wv[q2];
            ffma2(hA[2 * q2],     pa, w.x);
            ffma2(hA[2 * q2 + 1], pa, w.y);
            ffma2(hB[2 * q2],     pb, w.x);
            ffma2(hB[2 * q2 + 1], pb, w.y);
        }
    }
    // relu in place (keep packed pairs along j for the j-pair layer-2)
    #pragma unroll
    for (int q = 0; q < 26; ++q) {
        float a, b;
        unpack2(hA[q], a, b); hA[q] = pack2(fmaxf(a, 0.f), fmaxf(b, 0.f));
        unpack2(hB[q], a, b); hB[q] = pack2(fmaxf(a, 0.f), fmaxf(b, 0.f));
    }

    // ==== edge MLP layer 2: e2[k] = eb2[k] + sum_j h[j]*w2[j][k]  (j-pairs)
    float e2A[16], e2B[16];
    #pragma unroll
    for (int k = 0; k < 16; ++k) {
        unsigned long long aA = 0ULL, aB = 0ULL;
        const ulonglong2* wp = reinterpret_cast<const ulonglong2*>(&sw[OFF_EW2P + k * D2P]);
        #pragma unroll
        for (int q2 = 0; q2 < 13; ++q2) {
            ulonglong2 w = wp[q2];
            ffma2(aA, hA[2 * q2],     w.x);
            ffma2(aA, hA[2 * q2 + 1], w.y);
            ffma2(aB, hB[2 * q2],     w.x);
            ffma2(aB, hB[2 * q2 + 1], w.y);
        }
        float lo, hi;
        float bk = sw[OFF_EB2 + k];
        unpack2(aA, lo, hi); e2A[k] = lo + hi + bk;
        unpack2(aB, lo, hi); e2B[k] = lo + hi + bk;
    }

    // ==== node MLP layer 1: h2 = relu(nb1 + [x[col], e2] @ nw1)
    unsigned long long h2A[26], h2B[26];
    {
        const ulonglong2* bv = reinterpret_cast<const ulonglong2*>(&sw[OFF_NB1]);
        #pragma unroll
        for (int q2 = 0; q2 < 13; ++q2) {
            ulonglong2 b = bv[q2];
            h2A[2 * q2] = b.x; h2A[2 * q2 + 1] = b.y;
            h2B[2 * q2] = b.x; h2B[2 * q2 + 1] = b.y;
        }
    }
    #pragma unroll
    for (int i = 0; i < 18; ++i) {
        float xa = (i < 3) ? inA[3 + i] : e2A[i - 3];
        float xb = (i < 3) ? inB[3 + i] : e2B[i - 3];
        unsigned long long pa = pack2(xa, xa);
        unsigned long long pb = pack2(xb, xb);
        const ulonglong2* wv = reinterpret_cast<const ulonglong2*>(&sw[OFF_NW1 + i * D2P]);
        #pragma unroll
        for (int q2 = 0; q2 < 13; ++q2) {
            ulonglong2 w = wv[q2];
            ffma2(h2A[2 * q2],     pa, w.x);
            ffma2(h2A[2 * q2 + 1], pa, w.y);
            ffma2(h2B[2 * q2],     pb, w.x);
            ffma2(h2B[2 * q2 + 1], pb, w.y);
        }
    }
    #pragma unroll
    for (int q = 0; q < 26; ++q) {
        float a, b;
        unpack2(h2A[q], a, b); h2A[q] = pack2(fmaxf(a, 0.f), fmaxf(b, 0.f));
        unpack2(h2B[q], a, b); h2B[q] = pack2(fmaxf(a, 0.f), fmaxf(b, 0.f));
    }

    // ==== node MLP layer 2: o[k] = nb2[k] + sum_j h2[j]*nw2[j][k]  (j-pairs)
    float oA[16], oB[16];
    #pragma unroll
    for (int k = 0; k < 16; ++k) {
        unsigned long long aA = 0ULL, aB = 0ULL;
        const ulonglong2* wp = reinterpret_cast<const ulonglong2*>(&sw[OFF_NW2P + k * D2P]);
        #pragma unroll
        for (int q2 = 0; q2 < 13; ++q2) {
            ulonglong2 w = wp[q2];
            ffma2(aA, h2A[2 * q2],     w.x);
            ffma2(aA, h2A[2 * q2 + 1], w.y);
            ffma2(aB, h2B[2 * q2],     w.x);
            ffma2(aB, h2B[2 * q2 + 1], w.y);
        }
        float lo, hi;
        float bk = sw[OFF_NB2 + k];
        unpack2(aA, lo, hi); oA[k] = lo + hi + bk;
        unpack2(aB, lo, hi); oB[k] = lo + hi + bk;
    }
    oA[15] = 1.0f;  // count slot
    oB[15] = 1.0f;

    // ==== scatter
    {
        float* dst = &g_x2sum[(size_t)rA * 16];
        red4(dst + 0,  oA[0],  oA[1],  oA[2],  oA[3]);
        red4(dst + 4,  oA[4],  oA[5],  oA[6],  oA[7]);
        red4(dst + 8,  oA[8],  oA[9],  oA[10], oA[11]);
        red4(dst + 12, oA[12], oA[13], oA[14], oA[15]);
    }
    if (validB) {
        float* dst = &g_x2sum[(size_t)rB * 16];
        red4(dst + 0,  oB[0],  oB[1],  oB[2],  oB[3]);
        red4(dst + 4,  oB[4],  oB[5],  oB[6],  oB[7]);
        red4(dst + 8,  oB[8],  oB[9],  oB[10], oB[11]);
        red4(dst + 12, oB[12], oB[13], oB[14], oB[15]);
    }
}

// ---------------- graph kernel: per-graph reduce + global MLP + head -------
#define SG_GW1 0
#define SG_GB1 (SG_GW1 + 16 * D2)
#define SG_GW2 (SG_GB1 + D2)
#define SG_GB2 (SG_GW2 + D2 * D3)
#define SG_F1W (SG_GB2 + D3)
#define SG_F1B (SG_F1W + D3 * D5)
#define SG_BNG (SG_F1B + D5)
#define SG_BNB (SG_BNG + D5)
#define SG_F2W (SG_BNB + D5)
#define SG_F2B (SG_F2W + D5 * NC)
#define SG_TOTAL (SG_F2B + NC)

__device__ __forceinline__ int lbound(const int* a, int n, int key) {
    int lo = 0, hi = n;
    while (lo < hi) { int m = (lo + hi) >> 1; if (a[m] < key) lo = m + 1; else hi = m; }
    return lo;
}

__global__ void __launch_bounds__(256)
graph_kernel(
    const int* __restrict__ batch,
    const float* __restrict__ u,
    const float* __restrict__ gw1, const float* __restrict__ gb1,
    const float* __restrict__ gw2, const float* __restrict__ gb2,
    const float* __restrict__ fc1w, const float* __restrict__ fc1b,
    const float* __restrict__ bng, const float* __restrict__ bnb,
    const float* __restrict__ fc2w, const float* __restrict__ fc2b,
    float* __restrict__ out, int N)
{
    __shared__ float swt[SG_TOTAL];
    __shared__ float sred[8][30];
    __shared__ int sse[2];

    int tid = threadIdx.x;
    for (int t = tid; t < 16 * D2; t += blockDim.x) swt[SG_GW1 + t] = gw1[t];
    for (int t = tid; t < D2; t += blockDim.x) swt[SG_GB1 + t] = gb1[t];
    for (int t = tid; t < D2 * D3; t += blockDim.x) swt[SG_GW2 + t] = gw2[t];
    for (int t = tid; t < D3; t += blockDim.x) swt[SG_GB2 + t] = gb2[t];
    for (int t = tid; t < D3 * D5; t += blockDim.x) swt[SG_F1W + t] = fc1w[t];
    for (int t = tid; t < D5; t += blockDim.x) {
        swt[SG_F1B + t] = fc1b[t];
        swt[SG_BNG + t] = bng[t];
        swt[SG_BNB + t] = bnb[t];
    }
    for (int t = tid; t < D5 * NC; t += blockDim.x) swt[SG_F2W + t] = fc2w[t];
    for (int t = tid; t < NC; t += blockDim.x) swt[SG_F2B + t] = fc2b[t];

    int b = blockIdx.x;
    if (tid == 0) {
        sse[0] = lbound(batch, N, b);
        sse[1] = lbound(batch, N, b + 1);
    }
    __syncthreads();
    int s = sse[0], epos = sse[1];
    int nnodes = epos - s;

    float acc[30];
    #pragma unroll
    for (int k = 0; k < 30; ++k) acc[k] = 0.0f;

    for (int n = s + tid; n < epos; n += blockDim.x) {
        const float4* p = reinterpret_cast<const float4*>(&g_x2sum[(size_t)n * 16]);
        float4 a0 = p[0], a1 = p[1], a2 = p[2], a3 = p[3];
        float vv[15] = { a0.x, a0.y, a0.z, a0.w, a1.x, a1.y, a1.z, a1.w,
                         a2.x, a2.y, a2.z, a2.w, a3.x, a3.y, a3.z };
        float cnt = a3.w;
        float inv = 1.0f / fmaxf(cnt, 1.0f);
        #pragma unroll
        for (int k = 0; k < 15; ++k) {
            float t = vv[k] * inv;
            acc[k] += t;
            acc[15 + k] += fmaxf(t, 0.0f);
        }
    }

    #pragma unroll
    for (int k = 0; k < 30; ++k) {
        float v = acc[k];
        #pragma unroll
        for (int off = 16; off > 0; off >>= 1)
            v += __shfl_down_sync(0xFFFFFFFF, v, off);
        acc[k] = v;
    }
    int wid = tid >> 5, lid = tid & 31;
    if (lid == 0) {
        #pragma unroll
        for (int k = 0; k < 30; ++k) sred[wid][k] = acc[k];
    }
    __syncthreads();

    if (tid == 0) {
        float gsum[15], zsum[15];
        #pragma unroll
        for (int k = 0; k < 15; ++k) { gsum[k] = 0.0f; zsum[k] = 0.0f; }
        for (int w = 0; w < (int)(blockDim.x >> 5); ++w) {
            #pragma unroll
            for (int k = 0; k < 15; ++k) {
                gsum[k] += sred[w][k];
                zsum[k] += sred[w][15 + k];
            }
        }

        float cntf = (float)nnodes;
        float invc = 1.0f / fmaxf(cntf, 1.0f);

        float in16[16];
        in16[0] = u[b];
        #pragma unroll
        for (int k = 0; k < 15; ++k) in16[1 + k] = gsum[k] * invc;

        float hg[D2];
        #pragma unroll
        for (int j = 0; j < D2; ++j) hg[j] = swt[SG_GB1 + j];
        #pragma unroll
        for (int i = 0; i < 16; ++i) {
            float xi = in16[i];
            #pragma unroll
            for (int j = 0; j < D2; ++j) hg[j] += xi * swt[SG_GW1 + i * D2 + j];
        }
        #pragma unroll
        for (int j = 0; j < D2; ++j) hg[j] = fmaxf(hg[j], 0.0f);

        float u2[D3];
        #pragma unroll
        for (int k = 0; k < D3; ++k) u2[k] = swt[SG_GB2 + k];
        #pragma unroll
        for (int j = 0; j < D2; ++j) {
            float hj = hg[j];
            #pragma unroll
            for (int k = 0; k < D3; ++k) u2[k] += hj * swt[SG_GW2 + j * D3 + k];
        }

        float invg = 1.0f / (cntf + 1.0f);
        float g[D3];
        #pragma unroll
        for (int k = 0; k < D3; ++k)
            g[k] = (zsum[k] + fmaxf(u2[k], 0.0f)) * invg;

        float h1[D5];
        #pragma unroll
        for (int m = 0; m < D5; ++m) h1[m] = swt[SG_F1B + m];
        #pragma unroll
        for (int k = 0; k < D3; ++k) {
            float gk = g[k];
            #pragma unroll
            for (int m = 0; m < D5; ++m) h1[m] += gk * swt[SG_F1W + k * D5 + m];
        }

        float rs = rsqrtf(1.0f + 1e-5f);
        #pragma unroll
        for (int m = 0; m < D5; ++m)
            h1[m] = fmaxf(h1[m] * (swt[SG_BNG + m] * rs) + swt[SG_BNB + m], 0.0f);

        float lg[NC];
        #pragma unroll
        for (int q = 0; q < NC; ++q) lg[q] = swt[SG_F2B + q];
        #pragma unroll
        for (int m = 0; m < D5; ++m) {
            float hm = h1[m];
            #pragma unroll
            for (int q = 0; q < NC; ++q) lg[q] += hm * swt[SG_F2W + m * NC + q];
        }

        float mx = lg[0];
        #pragma unroll
        for (int q = 1; q < NC; ++q) mx = fmaxf(mx, lg[q]);
        float ssum = 0.0f;
        #pragma unroll
        for (int q = 0; q < NC; ++q) ssum += expf(lg[q] - mx);
        float lse = mx + logf(ssum);
        #pragma unroll
        for (int q = 0; q < NC; ++q) out[b * NC + q] = lg[q] - lse;
    }
}

// ---------------- launch ----------------
extern "C" void kernel_launch(void* const* d_in, const int* in_sizes, int n_in,
                              void* d_out, int out_size) {
    const float* x     = (const float*)d_in[0];
    const int*   ei    = (const int*)d_in[1];
    const float* ea    = (const float*)d_in[2];
    const float* u     = (const float*)d_in[3];
    const int*   batch = (const int*)d_in[4];
    const float* ew1   = (const float*)d_in[5];
    const float* eb1   = (const float*)d_in[6];
    const float* ew2   = (const float*)d_in[7];
    const float* eb2   = (const float*)d_in[8];
    const float* nw1   = (const float*)d_in[9];
    const float* nb1   = (const float*)d_in[10];
    const float* nw2   = (const float*)d_in[11];
    const float* nb2   = (const float*)d_in[12];
    const float* gw1   = (const float*)d_in[13];
    const float* gb1   = (const float*)d_in[14];
    const float* gw2   = (const float*)d_in[15];
    const float* gb2   = (const float*)d_in[16];
    const float* fc1w  = (const float*)d_in[17];
    const float* fc1b  = (const float*)d_in[18];
    const float* bng   = (const float*)d_in[19];
    const float* bnb   = (const float*)d_in[20];
    const float* fc2w  = (const float*)d_in[21];
    const float* fc2b  = (const float*)d_in[22];
    float* out = (float*)d_out;

    int N = in_sizes[0] / 3;   // nodes
    int E = in_sizes[1] / 2;   // edges
    int B = in_sizes[3];       // graphs

    const int* row = ei;
    const int* col = ei + E;

    zero_kernel<<<512, 256>>>(N);

    // edge pairs, split across 4 launches (ncu sampling + same total work)
    int P = (E + 1) / 2;
    int PQ = (P + 3) / 4;
    for (int q = 0; q < 4; ++q) {
        int p0 = q * PQ;
        int p1 = min(p0 + PQ, P);
        if (p0 >= p1) continue;
        int nthreads = p1 - p0;
        edge_kernel<<<(nthreads + 127) / 128, 128>>>(
            x, row, col, ea,
            ew1, eb1, ew2, eb2,
            nw1, nb1, nw2, nb2,
            p0, p1, E);
    }

    graph_kernel<<<B, 256>>>(batch, u,
                             gw1, gb1, gw2, gb2,
                             fc1w, fc1b, bng, bnb, fc2w, fc2b, out, N);
}